// round 6
// baseline (speedup 1.0000x reference)
#include <cuda_runtime.h>

// SplineNetwork, warp-per-query formulation.
// B=16384 queries, 128x128 regular grid, K=9 NN + Keys cubic conv.
//   d_in[0] = x (16384,2) f32 | d_in[1] = weights (16384,1) f32
//   d_in[2] = control_points (16384,2) f32, cp[i*128+j] = (t_i, t_j)
// Output: (out (16384,1), x (16384,2)) -> 49152 floats.
//
// One warp per query; lane i < 25 owns window candidate (i/5, i%5) of the
// ROUND-centered 5x5 window {nix-2..nix+2} clamped to [0,123] (R1/R4-certified:
// covers worst-case 9th-NN radius 2.06h interior, 2h edge, 2.83h corner, vs
// out-of-window >= 2.5h / 3h). D bit-matches the reference GEMM expansion:
//   D = rn(rn(x2s + c2) - 2*fma(x1,cy,rn(x0*cx)))
// Rank = #{j : D[j]<D[i] or (D[j]==D[i] and j<i)} via 24 modular shuffles;
// ties -> lower index == jax.lax.top_k stability. Selected iff rank < 9.

#define NGRID 128
#define WIN   5
#define NC    25
#define KNN   9

__global__ __launch_bounds__(256) void spline_warp_kernel(
    const float* __restrict__ x,
    const float* __restrict__ wts,
    const float* __restrict__ cp,
    float* __restrict__ out,
    int batch)
{
    const unsigned FULL = 0xffffffffu;
    int lane = threadIdx.x & 31;
    int q = blockIdx.x * (blockDim.x >> 5) + (threadIdx.x >> 5);
    if (q >= batch) return;

    // query point (uniform across warp -> broadcast load)
    float2 xv = __ldg((const float2*)x + q);
    float x0 = xv.x, x1 = xv.y;

    // bandwidth h = ||x[0]-x[1]|| (global constant; smooth, no bit-match needed)
    float4 h4 = __ldg((const float4*)x);
    float hdx = h4.x - h4.z;
    float hdy = h4.y - h4.w;
    float inv_h = 1.0f / sqrtf(__fadd_rn(__fmul_rn(hdx, hdx), __fmul_rn(hdy, hdy)));

    // round-centered window start, clamped (certified)
    int nix = __float2int_rn((x0 + 1.0f) * 63.5f);
    int niy = __float2int_rn((x1 + 1.0f) * 63.5f);
    int sx = min(max(nix - 2, 0), NGRID - WIN);
    int sy = min(max(niy - 2, 0), NGRID - WIN);

    // this lane's candidate (lanes >= 25 clamp to 24; their output is masked)
    int ci = (lane < NC) ? lane : (NC - 1);
    int rloc = ci / WIN;
    int cloc = ci - rloc * WIN;
    int ix = sx + rloc;
    int iy = sy + cloc;

    // node coords straight from cp (both equal linspace values exactly):
    //   x-coord of row ix = cp[(ix*128+0)*2 + 0], y-coord of col iy = cp[(0*128+iy)*2 + 1]
    float cx = __ldg(&cp[(ix << 8)]);
    float cy = __ldg(&cp[2 * iy + 1]);
    float wv = __ldg(&wts[(ix << 7) + iy]);

    // exact reference arithmetic for D
    float x2s = __fadd_rn(__fmul_rn(x0, x0), __fmul_rn(x1, x1));
    float c2  = __fadd_rn(__fmul_rn(cx, cx), __fmul_rn(cy, cy));
    float dot = __fmaf_rn(x1, cy, __fmul_rn(x0, cx));
    float D   = __fsub_rn(__fadd_rn(x2s, c2), __fmul_rn(2.0f, dot));
    if (lane >= NC) D = __int_as_float(0x7f800000);   // +inf: never selected

    // stable rank via modular all-to-all shuffles over the 25 real lanes
    int rank = 0;
#pragma unroll
    for (int k = 1; k < NC; ++k) {
        int j = lane + k;
        if (j >= NC) j -= NC;                 // for real lanes: covers all j != lane
        float Dj = __shfl_sync(FULL, D, j);
        bool jl = (Dj < D) || ((Dj == D) && (j < lane));
        rank += jl ? 1 : 0;
    }

    // Keys cubic conv epilogue (smooth; plain fp32)
    float dxv = x0 - cx;
    float dyv = x1 - cy;
    float a = sqrtf(fmaf(dxv, dxv, dyv * dyv)) * inv_h;
    float p1 = fmaf(fmaf(1.5f, a, -2.5f), a * a, 1.0f);
    float p2 = fmaf(fmaf(fmaf(-0.5f, a, 2.5f), a, -4.0f), a, 2.0f);
    float cv = (a < 1.0f) ? p1 : ((a < 2.0f) ? p2 : 0.0f);

    float val = (rank < KNN && lane < NC) ? (wv * cv) : 0.0f;

    // warp reduction
#pragma unroll
    for (int s = 16; s; s >>= 1)
        val += __shfl_xor_sync(FULL, val, s);

    if (lane == 0) {
        out[q] = val;
        ((float2*)(out + batch))[q] = xv;     // x passthrough
    }
}

extern "C" void kernel_launch(void* const* d_in, const int* in_sizes, int n_in,
                              void* d_out, int out_size)
{
    const float* x  = (const float*)d_in[0];
    const float* w  = (const float*)d_in[1];
    const float* cp = (const float*)d_in[2];
    float* out = (float*)d_out;
    int batch = in_sizes[0] / 2;              // 16384
    int block = 256;                          // 8 warps = 8 queries per CTA
    int warps_per_block = block / 32;
    int grid = (batch + warps_per_block - 1) / warps_per_block;   // 2048
    spline_warp_kernel<<<grid, block>>>(x, w, cp, out, batch);
    (void)n_in; (void)out_size;
}